// round 2
// baseline (speedup 1.0000x reference)
#include <cuda_runtime.h>
#include <cuda_bf16.h>

#define B_MAX 4096
#define D_FIXED 256
#define MAX_GAP 5
#define LOSS_W 0.1

// Scratch (no device allocs allowed)
__device__ double              g_loss;
__device__ unsigned long long  g_count;
__device__ int                 g_keys[B_MAX];

// ---------------------------------------------------------------------------
// Kernel A: pack (video<<16 | frame) keys, zero accumulators.
// NOTE: frame_numbers / video_ids arrive as int32 (JAX x64 disabled).
// ---------------------------------------------------------------------------
__global__ void prep_kernel(const int* __restrict__ frames,
                            const int* __restrict__ vids,
                            int B)
{
    int i = blockIdx.x * blockDim.x + threadIdx.x;
    if (i == 0) { g_loss = 0.0; g_count = 0ULL; }
    if (i < B) {
        int f = frames[i];   // 0..999  -> fits in 16 bits
        int v = vids[i];     // 0..15
        g_keys[i] = (v << 16) | (f & 0xFFFF);
    }
}

// ---------------------------------------------------------------------------
// Kernel B: one block per row i. Threads stride over j>i; key-compare filter,
// full distance only on mask hits.
// ---------------------------------------------------------------------------
__global__ void __launch_bounds__(256)
pair_kernel(const float* __restrict__ emb, int B)
{
    __shared__ float4 xi[D_FIXED / 4];       // 1 KB: row i
    __shared__ double s_loss[8];             // per-warp partials
    __shared__ unsigned int s_cnt[8];

    const int i   = blockIdx.x;
    const int tid = threadIdx.x;

    const float4* row_i = (const float4*)(emb + (size_t)i * D_FIXED);
    if (tid < D_FIXED / 4) xi[tid] = row_i[tid];
    __syncthreads();

    const int key_i   = g_keys[i];
    const int vid_i   = key_i >> 16;
    const int frame_i = key_i & 0xFFFF;

    double       loss = 0.0;
    unsigned int cnt  = 0;

    for (int j = i + 1 + tid; j < B; j += 256) {
        int key_j = g_keys[j];
        int df    = abs((key_j & 0xFFFF) - frame_i);
        if ((key_j >> 16) == vid_i && df <= MAX_GAP) {
            const float4* row_j = (const float4*)(emb + (size_t)j * D_FIXED);
            float acc = 0.0f;
            #pragma unroll 8
            for (int d = 0; d < D_FIXED / 4; d++) {
                float4 a = xi[d];
                float4 b = __ldg(&row_j[d]);
                float d0 = a.x - b.x, d1 = a.y - b.y;
                float d2 = a.z - b.z, d3 = a.w - b.w;
                acc = fmaf(d0, d0, acc);
                acc = fmaf(d1, d1, acc);
                acc = fmaf(d2, d2, acc);
                acc = fmaf(d3, d3, acc);
            }
            float w = 1.0f / (1.0f + (float)df);
            loss += (double)(w * acc * (1.0f / (float)D_FIXED));
            cnt  += 1u;
        }
    }

    // Warp reduction (double + uint)
    #pragma unroll
    for (int off = 16; off > 0; off >>= 1) {
        loss += __shfl_down_sync(0xFFFFFFFFu, loss, off);
        cnt  += __shfl_down_sync(0xFFFFFFFFu, cnt,  off);
    }
    int warp = tid >> 5;
    int lane = tid & 31;
    if (lane == 0) { s_loss[warp] = loss; s_cnt[warp] = cnt; }
    __syncthreads();

    if (warp == 0) {
        double l = (lane < 8) ? s_loss[lane] : 0.0;
        unsigned int c = (lane < 8) ? s_cnt[lane] : 0u;
        #pragma unroll
        for (int off = 4; off > 0; off >>= 1) {
            l += __shfl_down_sync(0xFFFFFFFFu, l, off);
            c += __shfl_down_sync(0xFFFFFFFFu, c, off);
        }
        if (lane == 0 && (l != 0.0 || c != 0u)) {
            atomicAdd(&g_loss, l);
            atomicAdd(&g_count, (unsigned long long)c);
        }
    }
}

// ---------------------------------------------------------------------------
// Kernel C: finalize scalar
// ---------------------------------------------------------------------------
__global__ void finalize_kernel(float* __restrict__ out)
{
    double c = (double)g_count;
    if (c < 1.0) c = 1.0;
    out[0] = (float)(LOSS_W * g_loss / c);
}

// ---------------------------------------------------------------------------
extern "C" void kernel_launch(void* const* d_in, const int* in_sizes, int n_in,
                              void* d_out, int out_size)
{
    const float* emb    = (const float*)d_in[0];
    const int*   frames = (const int*)d_in[1];
    const int*   vids   = (const int*)d_in[2];
    float*       out    = (float*)d_out;

    const int B = in_sizes[1];   // 4096 (D = 256, hardcoded)

    prep_kernel<<<(B + 255) / 256, 256>>>(frames, vids, B);
    pair_kernel<<<B, 256>>>(emb, B);
    finalize_kernel<<<1, 1>>>(out);
}

// round 3
// speedup vs baseline: 1.0861x; 1.0861x over previous
#include <cuda_runtime.h>
#include <cuda_bf16.h>

#define B_MAX    4096
#define D_FIXED  256
#define MAX_GAP  5
#define LOSS_W   0.1
#define NBLK     128
#define NTHR     256
#define NWARP    (NTHR / 32)
#define PAIR_CAP 6144          // 2048 drain threshold + 4095 worst-case single-row appends
#define DRAIN_AT 2048

// Per-block partials: written unconditionally each call -> no init kernel needed.
__device__ double       g_ploss[NBLK];
__device__ unsigned int g_pcnt[NBLK];

// ---------------------------------------------------------------------------
// Drain the shared pair list: one warp per pair, 32 lanes x 8 floats each.
// All threads of the block must call (contains __syncthreads).
// ---------------------------------------------------------------------------
__device__ __forceinline__ void drain_pairs(
    const float* __restrict__ emb,
    const int*  s_keys,
    unsigned int* s_pairs,
    int*  s_np,
    int   warp, int lane,
    double& loss, unsigned int& cnt)
{
    const int np = *s_np;
    for (int p = warp; p < np; p += NWARP) {
        const unsigned int pk = s_pairs[p];
        const int i = pk >> 16;
        const int j = pk & 0xFFFF;
        const float4* ri = (const float4*)(emb + (size_t)i * D_FIXED);
        const float4* rj = (const float4*)(emb + (size_t)j * D_FIXED);

        float4 a0 = ri[lane];        float4 b0 = rj[lane];
        float4 a1 = ri[lane + 32];   float4 b1 = rj[lane + 32];

        float d0 = a0.x - b0.x, d1 = a0.y - b0.y, d2 = a0.z - b0.z, d3 = a0.w - b0.w;
        float acc = d0 * d0;
        acc = fmaf(d1, d1, acc);  acc = fmaf(d2, d2, acc);  acc = fmaf(d3, d3, acc);
        d0 = a1.x - b1.x;  d1 = a1.y - b1.y;  d2 = a1.z - b1.z;  d3 = a1.w - b1.w;
        acc = fmaf(d0, d0, acc);  acc = fmaf(d1, d1, acc);
        acc = fmaf(d2, d2, acc);  acc = fmaf(d3, d3, acc);

        #pragma unroll
        for (int off = 16; off > 0; off >>= 1)
            acc += __shfl_down_sync(0xFFFFFFFFu, acc, off);

        if (lane == 0) {
            int df = abs((s_keys[i] & 0xFFFF) - (s_keys[j] & 0xFFFF));
            float w = 1.0f / (1.0f + (float)df);
            loss += (double)(acc * w * (1.0f / (float)D_FIXED));
            cnt  += 1u;
        }
    }
    __syncthreads();
    if (threadIdx.x == 0) *s_np = 0;
    __syncthreads();
}

// ---------------------------------------------------------------------------
// Main kernel: 128 blocks. Keys in smem, strided-row scan, fused distance.
// ---------------------------------------------------------------------------
__global__ void __launch_bounds__(NTHR)
main_kernel(const float* __restrict__ emb,
            const int*   __restrict__ frames,
            const int*   __restrict__ vids,
            int B)
{
    __shared__ int          s_keys[B_MAX];
    __shared__ unsigned int s_pairs[PAIR_CAP];
    __shared__ int          s_np;
    __shared__ double       s_loss[NWARP];
    __shared__ unsigned int s_cnt[NWARP];

    const int tid  = threadIdx.x;
    const int warp = tid >> 5;
    const int lane = tid & 31;

    for (int t = tid; t < B; t += NTHR)
        s_keys[t] = (vids[t] << 16) | (frames[t] & 0xFFFF);
    if (tid == 0) s_np = 0;
    __syncthreads();

    double       loss = 0.0;
    unsigned int cnt  = 0;

    // Strided rows: block b owns rows {b, b+128, ...} -> balanced triangle.
    for (int r = blockIdx.x; r < B; r += NBLK) {
        const int key_r   = s_keys[r];
        const int vid_r   = key_r >> 16;
        const int frame_r = key_r & 0xFFFF;

        for (int j = r + 1 + tid; j < B; j += NTHR) {
            const int kj = s_keys[j];
            const int df = abs((kj & 0xFFFF) - frame_r);
            if ((kj >> 16) == vid_r && df <= MAX_GAP) {
                int idx = atomicAdd(&s_np, 1);
                s_pairs[idx] = ((unsigned int)r << 16) | (unsigned int)j;
            }
        }
        __syncthreads();
        if (s_np >= DRAIN_AT)
            drain_pairs(emb, s_keys, s_pairs, &s_np, warp, lane, loss, cnt);
    }
    drain_pairs(emb, s_keys, s_pairs, &s_np, warp, lane, loss, cnt);

    // Block reduction (loss/cnt nonzero only on lane 0 of each warp, but
    // reduce all lanes for generality).
    #pragma unroll
    for (int off = 16; off > 0; off >>= 1) {
        loss += __shfl_down_sync(0xFFFFFFFFu, loss, off);
        cnt  += __shfl_down_sync(0xFFFFFFFFu, cnt,  off);
    }
    if (lane == 0) { s_loss[warp] = loss; s_cnt[warp] = cnt; }
    __syncthreads();

    if (warp == 0) {
        double       l = (lane < NWARP) ? s_loss[lane] : 0.0;
        unsigned int c = (lane < NWARP) ? s_cnt[lane]  : 0u;
        #pragma unroll
        for (int off = 4; off > 0; off >>= 1) {
            l += __shfl_down_sync(0xFFFFFFFFu, l, off);
            c += __shfl_down_sync(0xFFFFFFFFu, c, off);
        }
        if (lane == 0) {
            g_ploss[blockIdx.x] = l;          // unconditional -> no init needed
            g_pcnt[blockIdx.x]  = c;
        }
    }
}

// ---------------------------------------------------------------------------
// Finalize: reduce 128 partials, write scalar.
// ---------------------------------------------------------------------------
__global__ void finalize_kernel(float* __restrict__ out)
{
    __shared__ double       s_l[4];
    __shared__ unsigned int s_c[4];
    const int tid  = threadIdx.x;        // 128 threads
    const int warp = tid >> 5;
    const int lane = tid & 31;

    double       l = g_ploss[tid];
    unsigned int c = g_pcnt[tid];
    #pragma unroll
    for (int off = 16; off > 0; off >>= 1) {
        l += __shfl_down_sync(0xFFFFFFFFu, l, off);
        c += __shfl_down_sync(0xFFFFFFFFu, c, off);
    }
    if (lane == 0) { s_l[warp] = l; s_c[warp] = c; }
    __syncthreads();

    if (tid == 0) {
        double       L = s_l[0] + s_l[1] + s_l[2] + s_l[3];
        double       C = (double)(s_c[0] + s_c[1] + s_c[2] + s_c[3]);
        if (C < 1.0) C = 1.0;
        out[0] = (float)(LOSS_W * L / C);
    }
}

// ---------------------------------------------------------------------------
extern "C" void kernel_launch(void* const* d_in, const int* in_sizes, int n_in,
                              void* d_out, int out_size)
{
    const float* emb    = (const float*)d_in[0];
    const int*   frames = (const int*)d_in[1];
    const int*   vids   = (const int*)d_in[2];
    float*       out    = (float*)d_out;

    const int B = in_sizes[1];   // 4096 (D = 256 hardcoded)

    main_kernel<<<NBLK, NTHR>>>(emb, frames, vids, B);
    finalize_kernel<<<1, 128>>>(out);
}